// round 6
// baseline (speedup 1.0000x reference)
#include <cuda_runtime.h>
#include <math.h>
#include <stdint.h>

#define NN 50000
#define EE 400000
#define FF 128
#define F3 384
#define NRBF 20
#define EPAD (EE + NN)
#define EP 450560
#define CHUNK 32

typedef unsigned long long u64;

// ---------------- f32x2 packed helpers ----------------
__device__ __forceinline__ u64 pk2(float a, float b) {
    u64 r; asm("mov.b64 %0,{%1,%2};" : "=l"(r) : "f"(a), "f"(b)); return r;
}
__device__ __forceinline__ u64 pkdup(float a) {
    u64 r; asm("mov.b64 %0,{%1,%1};" : "=l"(r) : "f"(a)); return r;
}
__device__ __forceinline__ float2 upk(u64 v) {
    float2 f; asm("mov.b64 {%0,%1},%2;" : "=f"(f.x), "=f"(f.y) : "l"(v)); return f;
}
__device__ __forceinline__ u64 f2fma(u64 a, u64 b, u64 c) {
    u64 d; asm("fma.rn.f32x2 %0,%1,%2,%3;" : "=l"(d) : "l"(a), "l"(b), "l"(c)); return d;
}
__device__ __forceinline__ u64 f2add(u64 a, u64 b) {
    u64 d; asm("add.rn.f32x2 %0,%1,%2;" : "=l"(d) : "l"(a), "l"(b)); return d;
}

// ---------------- tf32 helpers ----------------
__device__ __forceinline__ uint32_t to_tf32(float f) {
    uint32_t u; asm("cvt.rna.tf32.f32 %0, %1;" : "=r"(u) : "f"(f)); return u;
}
__device__ __forceinline__ void mma_tf32(float c[4], uint32_t a0, uint32_t a1,
                                         uint32_t a2, uint32_t a3,
                                         uint32_t b0, uint32_t b1) {
    asm("mma.sync.aligned.m16n8k8.row.col.f32.tf32.tf32.f32 "
        "{%0,%1,%2,%3},{%4,%5,%6,%7},{%8,%9},{%0,%1,%2,%3};"
        : "+f"(c[0]), "+f"(c[1]), "+f"(c[2]), "+f"(c[3])
        : "r"(a0), "r"(a1), "r"(a2), "r"(a3), "r"(b0), "r"(b1));
}

// ---------------- scratch ----------------
__device__ float g_phi[NN * F3];
__device__ float g_h[NN * FF];
__device__ float g_rbf[NRBF * EP];
__device__ float g_dirx[EP];
__device__ float g_diry[EP];
__device__ float g_dirz[EP];
__device__ int   g_cnt[NN];
__device__ int   g_off[NN];
__device__ int   g_cur[NN];
__device__ int   g_order[EPAD];

// ---------------- CSR build ----------------
__global__ void k_init() {
    int i = blockIdx.x * blockDim.x + threadIdx.x;
    if (i < NN) g_cnt[i] = 0;
    if (i < EPAD) g_order[i] = -1;
}

__global__ void k_hist(const float* __restrict__ r) {
    int e = blockIdx.x * blockDim.x + threadIdx.x;
    if (e < EE) {
        int j = (int)r[e * 5 + 1];
        atomicAdd(&g_cnt[j], 1);
    }
}

__global__ void k_scan() {
    __shared__ int part[1024];
    int t = threadIdx.x;
    const int CH = (NN + 1023) / 1024;
    int base = t * CH, sum = 0;
    for (int i = 0; i < CH; i++) {
        int idx = base + i;
        if (idx < NN) sum += (g_cnt[idx] + 1) & ~1;
    }
    part[t] = sum;
    __syncthreads();
    for (int off = 1; off < 1024; off <<= 1) {
        int v = (t >= off) ? part[t - off] : 0;
        __syncthreads();
        part[t] += v;
        __syncthreads();
    }
    int run = (t > 0) ? part[t - 1] : 0;
    for (int i = 0; i < CH; i++) {
        int idx = base + i;
        if (idx < NN) {
            g_off[idx] = run;
            g_cur[idx] = run;
            run += (g_cnt[idx] + 1) & ~1;
        }
    }
}

__global__ void k_fill(const float* __restrict__ r) {
    int e = blockIdx.x * blockDim.x + threadIdx.x;
    if (e < EE) {
        int j = (int)r[e * 5 + 1];
        int pos = atomicAdd(&g_cur[j], 1);
        g_order[pos] = e;
    }
}

__global__ void k_sortlists() {
    int n = blockIdx.x * blockDim.x + threadIdx.x;
    if (n >= NN) return;
    int s0 = g_off[n], s1 = s0 + g_cnt[n];
    for (int i = s0 + 1; i < s1; i++) {
        int key = g_order[i];
        int j = i - 1;
        while (j >= s0 && g_order[j] > key) {
            g_order[j + 1] = g_order[j];
            j--;
        }
        g_order[j + 1] = key;
    }
}

// ---------------- per-edge precompute ----------------
__global__ void k_edge(const float* __restrict__ r) {
    int p = blockIdx.x * blockDim.x + threadIdx.x;
    if (p >= EPAD) return;
    int eid = g_order[p];
    if (eid < 0) {
#pragma unroll
        for (int k = 0; k < NRBF; k++) g_rbf[k * EP + p] = 0.0f;
        g_dirx[p] = 0.0f; g_diry[p] = 0.0f; g_dirz[p] = 0.0f;
        return;
    }
    float rx = r[eid * 5 + 2];
    float ry = r[eid * 5 + 3];
    float rz = r[eid * 5 + 4];
    float z = fabsf(rz);
    float inv = 1.0f / (z + 1e-8f);
    float th = 0.6283185307179586f * z;
    float s, c;
    sincosf(th, &s, &c);
    float twoc = 2.0f * c;
    float skm = 0.0f, sk = s;
#pragma unroll
    for (int k = 0; k < NRBF; k++) {
        g_rbf[k * EP + p] = sk * inv;
        float nxt = fmaf(twoc, sk, -skm);
        skm = sk; sk = nxt;
    }
    float nrm = sqrtf(rx * rx + ry * ry + rz * rz);
    float invn = 1.0f / (nrm + 1e-8f);
    g_dirx[p] = rx * invn;
    g_diry[p] = ry * invn;
    g_dirz[p] = rz * invn;
}

// ---------------- 3xTF32 tensor-core GEMM ----------------
// C = act(A@B + bias); A:[M,K] row-major, B:[K,N] row-major.
// BM=128, BN=64, BK=16; 256 threads = 8 warps (4 m x 2 n); warp tile 32x32.
template <bool SILU>
__global__ void __launch_bounds__(256) k_gemm_tc(const float* __restrict__ A,
                                                 const float* __restrict__ B,
                                                 const float* __restrict__ bias,
                                                 float* __restrict__ C,
                                                 int M, int N, int K) {
    __shared__ float Ah[16][132];
    __shared__ float Al[16][132];
    __shared__ float Bh[16][68];
    __shared__ float Bl[16][68];

    int t = threadIdx.x;
    int lane = t & 31;
    int wid = t >> 5;
    int warp_m = wid >> 1;          // 0..3
    int warp_n = wid & 1;           // 0..1
    int qrow = lane >> 2;           // 0..7
    int qcol = lane & 3;            // 0..3

    int rowBase = blockIdx.y * 128;
    int colBase = blockIdx.x * 64;

    float acc[2][4][4];
#pragma unroll
    for (int i = 0; i < 2; i++)
#pragma unroll
        for (int j = 0; j < 4; j++)
#pragma unroll
            for (int q = 0; q < 4; q++) acc[i][j][q] = 0.0f;

    for (int kt = 0; kt < K; kt += 16) {
        // stage A tile (128 x 16) as hi/lo tf32, transposed [k][m]
#pragma unroll
        for (int h = 0; h < 2; h++) {
            int slot = t * 2 + h;          // 0..511
            int row = slot >> 2;
            int kq = (slot & 3) << 2;
            int grow = rowBase + row;
            float4 a4 = make_float4(0.f, 0.f, 0.f, 0.f);
            if (grow < M) a4 = *(const float4*)&A[grow * K + kt + kq];
            float av[4] = {a4.x, a4.y, a4.z, a4.w};
#pragma unroll
            for (int j = 0; j < 4; j++) {
                uint32_t hb = to_tf32(av[j]);
                float hf = __uint_as_float(hb);
                float lo = av[j] - hf;
                Ah[kq + j][row] = hf;
                Al[kq + j][row] = __uint_as_float(to_tf32(lo));
            }
        }
        // stage B tile (16 x 64) as hi/lo tf32
        {
            int row = t >> 4;              // 0..15
            int c4 = (t & 15) << 2;        // 0..60
            float4 b4 = *(const float4*)&B[(kt + row) * N + colBase + c4];
            float bv[4] = {b4.x, b4.y, b4.z, b4.w};
#pragma unroll
            for (int j = 0; j < 4; j++) {
                uint32_t hb = to_tf32(bv[j]);
                float hf = __uint_as_float(hb);
                float lo = bv[j] - hf;
                Bh[row][c4 + j] = hf;
                Bl[row][c4 + j] = __uint_as_float(to_tf32(lo));
            }
        }
        __syncthreads();

#pragma unroll
        for (int ks = 0; ks < 16; ks += 8) {
            // A fragments (hi & lo) for 2 m-tiles
            uint32_t ah[2][4], al[2][4];
#pragma unroll
            for (int i = 0; i < 2; i++) {
                int m0 = warp_m * 32 + i * 16 + qrow;
                ah[i][0] = __float_as_uint(Ah[ks + qcol][m0]);
                ah[i][1] = __float_as_uint(Ah[ks + qcol][m0 + 8]);
                ah[i][2] = __float_as_uint(Ah[ks + qcol + 4][m0]);
                ah[i][3] = __float_as_uint(Ah[ks + qcol + 4][m0 + 8]);
                al[i][0] = __float_as_uint(Al[ks + qcol][m0]);
                al[i][1] = __float_as_uint(Al[ks + qcol][m0 + 8]);
                al[i][2] = __float_as_uint(Al[ks + qcol + 4][m0]);
                al[i][3] = __float_as_uint(Al[ks + qcol + 4][m0 + 8]);
            }
            // B fragments (hi & lo) for 4 n-tiles
            uint32_t bh[4][2], bl[4][2];
#pragma unroll
            for (int j = 0; j < 4; j++) {
                int n0 = warp_n * 32 + j * 8 + qrow;
                bh[j][0] = __float_as_uint(Bh[ks + qcol][n0]);
                bh[j][1] = __float_as_uint(Bh[ks + qcol + 4][n0]);
                bl[j][0] = __float_as_uint(Bl[ks + qcol][n0]);
                bl[j][1] = __float_as_uint(Bl[ks + qcol + 4][n0]);
            }
#pragma unroll
            for (int i = 0; i < 2; i++)
#pragma unroll
                for (int j = 0; j < 4; j++) {
                    mma_tf32(acc[i][j], ah[i][0], ah[i][1], ah[i][2], ah[i][3],
                             bh[j][0], bh[j][1]);
                    mma_tf32(acc[i][j], ah[i][0], ah[i][1], ah[i][2], ah[i][3],
                             bl[j][0], bl[j][1]);
                    mma_tf32(acc[i][j], al[i][0], al[i][1], al[i][2], al[i][3],
                             bh[j][0], bh[j][1]);
                }
        }
        __syncthreads();
    }

    // epilogue: bias + optional silu, write C
#pragma unroll
    for (int i = 0; i < 2; i++) {
#pragma unroll
        for (int j = 0; j < 4; j++) {
            int col0 = colBase + warp_n * 32 + j * 8 + 2 * qcol;
            float bv0 = bias[col0], bv1 = bias[col0 + 1];
#pragma unroll
            for (int h = 0; h < 2; h++) {
                int grow = rowBase + warp_m * 32 + i * 16 + qrow + h * 8;
                if (grow < M) {
                    float o0 = acc[i][j][2 * h] + bv0;
                    float o1 = acc[i][j][2 * h + 1] + bv1;
                    if (SILU) {
                        o0 = o0 / (1.0f + __expf(-o0));
                        o1 = o1 / (1.0f + __expf(-o1));
                    }
                    *(float2*)&C[grow * N + col0] = make_float2(o0, o1);
                }
            }
        }
    }
}

// ---------------- cutoff via MUFU ----------------
__device__ __forceinline__ float cw(float x) {
    float c = __cosf(x * 0.6283185307179586f);
    float w = fmaf(c, 0.5f, 0.5f);
    return (x < 5.0f) ? w : 0.0f;
}

// ---------------- main per-node kernel ----------------
__global__ void __launch_bounds__(128) k_main(const float* __restrict__ v,
                                              const float* __restrict__ Wr,
                                              const float* __restrict__ br,
                                              float* __restrict__ out) {
    __shared__ u64 sm[23][CHUNK];
    int t = threadIdx.x;

    u64 wr0d[NRBF], wr1d[NRBF], wr2d[NRBF];
#pragma unroll
    for (int k = 0; k < NRBF; k++) {
        wr0d[k] = pkdup(Wr[k * F3 + t]);
        wr1d[k] = pkdup(Wr[k * F3 + FF + t]);
        wr2d[k] = pkdup(Wr[k * F3 + 2 * FF + t]);
    }
    u64 br0d = pkdup(br[t]), br1d = pkdup(br[FF + t]), br2d = pkdup(br[2 * FF + t]);

    for (int n = blockIdx.x; n < NN; n += gridDim.x) {
        int base = g_off[n];
        int cnt = g_cnt[n];
        int npairs = (cnt + 1) >> 1;
        u64 accA = 0ull, accB = 0ull, bx = 0ull, by = 0ull, bz = 0ull;

        for (int cs = 0; cs < npairs; cs += CHUNK) {
            int nc = npairs - cs; if (nc > CHUNK) nc = CHUNK;
            __syncthreads();
            {
                int pbase = base + (cs << 1);
#pragma unroll
                for (int idx = 0; idx < 6; idx++) {
                    int q = t + idx * 128;
                    if (q < 23 * CHUNK) {
                        int j = q >> 5;
                        int i = q & 31;
                        const float* rowp;
                        if (j < NRBF)      rowp = g_rbf + j * EP + pbase;
                        else if (j == 20)  rowp = g_dirx + pbase;
                        else if (j == 21)  rowp = g_diry + pbase;
                        else               rowp = g_dirz + pbase;
                        sm[j][i] = *(const u64*)(rowp + (i << 1));
                    }
                }
            }
            __syncthreads();
            for (int i = 0; i < nc; i++) {
                u64 x0 = br0d, x1 = br1d, x2 = br2d;
#pragma unroll
                for (int k = 0; k < NRBF; k++) {
                    u64 rr = sm[k][i];
                    x0 = f2fma(rr, wr0d[k], x0);
                    x1 = f2fma(rr, wr1d[k], x1);
                    x2 = f2fma(rr, wr2d[k], x2);
                }
                float2 v0 = upk(x0), v1 = upk(x1), v2 = upk(x2);
                u64 W0 = pk2(cw(v0.x), cw(v0.y));
                u64 W1 = pk2(cw(v1.x), cw(v1.y));
                u64 W2 = pk2(cw(v2.x), cw(v2.y));
                u64 m = (((cs + i) << 1) + 1 < cnt) ? ~0ull : 0xFFFFFFFFull;
                accA = f2add(accA, W0 & m);
                accB = f2add(accB, W1 & m);
                bx = f2fma(W2, sm[20][i], bx);
                by = f2fma(W2, sm[21][i], by);
                bz = f2fma(W2, sm[22][i], bz);
            }
        }
        float2 rA = upk(accA), rB = upk(accB);
        float2 rx = upk(bx), ry = upk(by), rz = upk(bz);
        float a1 = rA.x + rA.y;
        float a2 = rB.x + rB.y;
        float cx = rx.x + rx.y;
        float cy = ry.x + ry.y;
        float cz = rz.x + rz.y;

        float ph1 = g_phi[n * F3 + t];
        float ph2 = g_phi[n * F3 + FF + t];
        float ph3 = g_phi[n * F3 + 2 * FF + t];
        int nf = n * FF + t;
        float vx = v[nf * 3 + 0], vy = v[nf * 3 + 1], vz = v[nf * 3 + 2];
        float s1v = ph1 * a1;
        out[nf * 3 + 0] = fmaf(vx, s1v, ph3 * cx);
        out[nf * 3 + 1] = fmaf(vy, s1v, ph3 * cy);
        out[nf * 3 + 2] = fmaf(vz, s1v, ph3 * cz);
        out[NN * F3 + nf] = ph2 * a2;
    }
}

// ---------------- launch ----------------
extern "C" void kernel_launch(void* const* d_in, const int* in_sizes, int n_in,
                              void* d_out, int out_size) {
    (void)in_sizes; (void)n_in; (void)out_size;
    const float* v  = (const float*)d_in[0];
    const float* s  = (const float*)d_in[1];
    const float* r  = (const float*)d_in[2];
    const float* W1 = (const float*)d_in[3];
    const float* b1 = (const float*)d_in[4];
    const float* W2 = (const float*)d_in[5];
    const float* b2 = (const float*)d_in[6];
    const float* Wr = (const float*)d_in[7];
    const float* br = (const float*)d_in[8];
    float* out = (float*)d_out;

    void* q;
    cudaGetSymbolAddress(&q, g_h);
    float* hptr = (float*)q;
    cudaGetSymbolAddress(&q, g_phi);
    float* pptr = (float*)q;

    k_init<<<(EPAD + 255) / 256, 256>>>();
    k_hist<<<(EE + 255) / 256, 256>>>(r);
    k_scan<<<1, 1024>>>();
    // tensor-core GEMMs (launch idx 3 = gemm1 stays the ncu capture slot)
    {
        dim3 g1(FF / 64, (NN + 127) / 128);
        k_gemm_tc<true><<<g1, 256>>>(s, W1, b1, hptr, NN, FF, FF);
        dim3 g2(F3 / 64, (NN + 127) / 128);
        k_gemm_tc<false><<<g2, 256>>>(hptr, W2, b2, pptr, NN, F3, FF);
    }
    k_fill<<<(EE + 255) / 256, 256>>>(r);
    k_sortlists<<<(NN + 127) / 128, 128>>>();
    k_edge<<<(EPAD + 127) / 128, 128>>>(r);
    k_main<<<2048, 128>>>(v, Wr, br, out);
}